// round 6
// baseline (speedup 1.0000x reference)
#include <cuda_runtime.h>
#include <cuda_fp16.h>
#include <stdint.h>

#define NB   8
#define NC   256
#define NPIX 4096
#define KST  768      // stacked K: [x_h; x_l; x_h(reused)]
#define KSL  512      // stored slabs (hi, lo)
#define MR   320      // 32 q + 32 k + 256 v output channels
#define LOG2E 1.4426950408889634f

// ---------------- scratch (device globals; no allocation) ----------------
__device__ __half g_xs[(size_t)NB * KSL * NPIX];   // 33.5 MB stacked x (fp16 hi/lo)
__device__ __half g_ws[MR * KST];                  // stacked weights
__device__ __half g_qT[(size_t)NB * NPIX * 32];    // [b][n][d]  (q pre-scaled by log2e)
__device__ __half g_kT[(size_t)NB * NPIX * 32];    // [b][n][d]
__device__ __half g_vT[(size_t)NB * NPIX * NC];    // [b][n][c]
__device__ float  g_rowmax[(size_t)NB * NPIX];     // per-row score max (log2 domain)

// ---------------- mma / ldmatrix / cp.async helpers ----------------
__device__ __forceinline__ unsigned smem_u32(const void* p) {
    return (unsigned)__cvta_generic_to_shared(p);
}
__device__ __forceinline__ uint32_t h2_as_u32(__half2 h) {
    return *reinterpret_cast<uint32_t*>(&h);
}
__device__ __forceinline__ uint32_t h2exp2(uint32_t x) {
    uint32_t r;
    asm("ex2.approx.f16x2 %0, %1;" : "=r"(r) : "r"(x));
    return r;
}
__device__ __forceinline__ void ldm_x4(uint32_t* r, unsigned addr) {
    asm volatile("ldmatrix.sync.aligned.m8n8.x4.shared.b16 {%0,%1,%2,%3}, [%4];\n"
                 : "=r"(r[0]), "=r"(r[1]), "=r"(r[2]), "=r"(r[3]) : "r"(addr));
}
__device__ __forceinline__ void ldm_x4_t(uint32_t* r, unsigned addr) {
    asm volatile("ldmatrix.sync.aligned.m8n8.x4.trans.shared.b16 {%0,%1,%2,%3}, [%4];\n"
                 : "=r"(r[0]), "=r"(r[1]), "=r"(r[2]), "=r"(r[3]) : "r"(addr));
}
__device__ __forceinline__ void mma_16816(float* d, const uint32_t* a, uint32_t b0, uint32_t b1) {
    asm volatile(
        "mma.sync.aligned.m16n8k16.row.col.f32.f16.f16.f32 "
        "{%0,%1,%2,%3},{%4,%5,%6,%7},{%8,%9},{%0,%1,%2,%3};\n"
        : "+f"(d[0]), "+f"(d[1]), "+f"(d[2]), "+f"(d[3])
        : "r"(a[0]), "r"(a[1]), "r"(a[2]), "r"(a[3]), "r"(b0), "r"(b1));
}
__device__ __forceinline__ void cp_async16(unsigned dst, const void* src) {
    asm volatile("cp.async.cg.shared.global [%0], [%1], 16;\n" :: "r"(dst), "l"(src));
}
__device__ __forceinline__ void cp_commit() {
    asm volatile("cp.async.commit_group;\n");
}
template <int N>
__device__ __forceinline__ void cp_wait() {
    asm volatile("cp.async.wait_group %0;\n" :: "n"(N));
}

// ---------------- pack kernels ----------------
__global__ void pack_w_kernel(const float* __restrict__ wq, const float* __restrict__ wk,
                              const float* __restrict__ wv) {
    int idx = blockIdx.x * blockDim.x + threadIdx.x;
    if (idx >= MR * NC) return;
    int k = idx & 255;
    int m = idx >> 8;
    float w = (m < 32) ? wq[m * NC + k] * LOG2E
            : (m < 64) ? wk[(m - 32) * NC + k]
                       : wv[(m - 64) * NC + k];
    __half hi = __float2half_rn(w);
    __half lo = __float2half_rn(w - __half2float(hi));
    g_ws[m * KST + k]       = hi;   // pairs with x_h
    g_ws[m * KST + 256 + k] = hi;   // pairs with x_l
    g_ws[m * KST + 512 + k] = lo;   // pairs with x_h (re-read slab 0)
}

__global__ void pack_x_kernel(const float* __restrict__ x) {
    int idx = blockIdx.x * blockDim.x + threadIdx.x;  // one float4 each
    const int total = NB * NC * NPIX / 4;
    if (idx >= total) return;
    float4 v = ((const float4*)x)[idx];
    int n4 = idx % (NPIX / 4);
    int t  = idx / (NPIX / 4);
    int c  = t % NC;
    int b  = t / NC;
    float f[4] = {v.x, v.y, v.z, v.w};
    __align__(8) __half hi[4], lo[4];
#pragma unroll
    for (int i = 0; i < 4; i++) {
        hi[i] = __float2half_rn(f[i]);
        lo[i] = __float2half_rn(f[i] - __half2float(hi[i]));
    }
    size_t base = ((size_t)b * KSL) * NPIX + (size_t)n4 * 4;
    *(uint2*)&g_xs[base + (size_t)c * NPIX]         = *(uint2*)&hi[0];
    *(uint2*)&g_xs[base + (size_t)(c + 256) * NPIX] = *(uint2*)&lo[0];
}

// ---------------- projection GEMM: C[320,4096] = Ws[320,768] * Xs[768,4096] ----------------
#define PA_STR 40
#define PB_STR 72

__global__ __launch_bounds__(128) void proj_kernel(const float* __restrict__ bq,
                                                   const float* __restrict__ bk,
                                                   const float* __restrict__ bv) {
    __shared__ __half a_s[64 * PA_STR];
    __shared__ __half b_s[32 * PB_STR];
    __shared__ __half c_s[64 * PB_STR];

    int n0 = blockIdx.x * 64;
    int m0 = blockIdx.y * 64;
    int b  = blockIdx.z;
    int tid = threadIdx.x;
    int w = tid >> 5, lane = tid & 31;
    int g = lane >> 2, t4 = lane & 3;

    float acc[8][4];
#pragma unroll
    for (int i = 0; i < 8; i++)
#pragma unroll
        for (int j = 0; j < 4; j++) acc[i][j] = 0.f;

    const __half* gA = &g_ws[m0 * KST];
    const __half* gB = &g_xs[(size_t)b * KSL * NPIX + n0];

    for (int kt = 0; kt < KST / 32; kt++) {
        int k0 = kt * 32;
        int kk = (k0 < KSL) ? k0 : (k0 - KSL);  // hi slab re-read for lo-weight rows
        __syncthreads();
#pragma unroll
        for (int p = 0; p < 2; p++) {  // A: 64x32
            int e = (tid + p * 128) * 8;
            int r = e >> 5, c = e & 31;
            *(uint4*)&a_s[r * PA_STR + c] = *(const uint4*)&gA[r * KST + k0 + c];
        }
#pragma unroll
        for (int p = 0; p < 2; p++) {  // B: 32x64
            int e = (tid + p * 128) * 8;
            int r = e >> 6, c = e & 63;
            *(uint4*)&b_s[r * PB_STR + c] = *(const uint4*)&gB[(size_t)(kk + r) * NPIX + c];
        }
        __syncthreads();
#pragma unroll
        for (int ks = 0; ks < 2; ks++) {
            uint32_t af[4];
            {
                int row = 16 * w + (lane & 15);
                int col = 16 * ks + ((lane >= 16) ? 8 : 0);
                ldm_x4(af, smem_u32(&a_s[row * PA_STR + col]));
            }
#pragma unroll
            for (int nbp = 0; nbp < 4; nbp++) {
                uint32_t bf[4];
                int row = 16 * ks + (lane & 15);
                int col = 16 * nbp + ((lane >= 16) ? 8 : 0);
                ldm_x4_t(bf, smem_u32(&b_s[row * PB_STR + col]));
                mma_16816(acc[2 * nbp],     af, bf[0], bf[1]);
                mma_16816(acc[2 * nbp + 1], af, bf[2], bf[3]);
            }
        }
    }
    __syncthreads();
    // bias + fp16 stage
    int row_a = 16 * w + g;
    int row_b = row_a + 8;
    int ma = m0 + row_a, mb = m0 + row_b;
    float bias_a = (ma < 32) ? bq[ma] * LOG2E : (ma < 64) ? bk[ma - 32] : bv[ma - 64];
    float bias_b = (mb < 32) ? bq[mb] * LOG2E : (mb < 64) ? bk[mb - 32] : bv[mb - 64];
#pragma unroll
    for (int nt = 0; nt < 8; nt++) {
        int col = 8 * nt + 2 * t4;
        c_s[row_a * PB_STR + col]     = __float2half_rn(acc[nt][0] + bias_a);
        c_s[row_a * PB_STR + col + 1] = __float2half_rn(acc[nt][1] + bias_a);
        c_s[row_b * PB_STR + col]     = __float2half_rn(acc[nt][2] + bias_b);
        c_s[row_b * PB_STR + col + 1] = __float2half_rn(acc[nt][3] + bias_b);
    }
    __syncthreads();
    // transposed coalesced writeback
    int n = tid & 63, part = tid >> 6;
    __align__(16) __half tmp[32];
#pragma unroll
    for (int j = 0; j < 32; j++) tmp[j] = c_s[(part * 32 + j) * PB_STR + n];
    int ng = n0 + n;
    __half* dst;
    if (m0 == 0) {
        dst = (part == 0) ? &g_qT[((size_t)b * NPIX + ng) * 32]
                          : &g_kT[((size_t)b * NPIX + ng) * 32];
    } else {
        int cb = (m0 - 64) + part * 32;
        dst = &g_vT[((size_t)b * NPIX + ng) * NC + cb];
    }
#pragma unroll
    for (int q = 0; q < 4; q++) ((uint4*)dst)[q] = ((uint4*)tmp)[q];
}

// ---------------- pass 1: per-row score max over all keys ----------------
// Grid (NPIX/64, NB), 256 threads. Warp (mw, nh): rows [16*mw,+16), keys nh-half of a
// 128-key chunk. Same MMA sequence as flash -> bitwise-identical S -> s - m <= 0.
__global__ __launch_bounds__(256) void qk_max_kernel() {
    __shared__ __half q_s[64 * 40];
    __shared__ __half k_s[2][128 * 40];
    __shared__ float partial[2][64];

    int nq0 = blockIdx.x * 64;
    int b   = blockIdx.y;
    int tid = threadIdx.x;
    int w = tid >> 5, lane = tid & 31, g = lane >> 2;
    int mw = w & 3, nh = w >> 2;

    {   // Q tile 64x32
        int e = tid * 8;
        int r = e >> 5, c = e & 31;
        *(uint4*)&q_s[r * 40 + c] = *(const uint4*)&g_qT[((size_t)b * NPIX + nq0 + r) * 32 + c];
    }
    {   // prefetch K chunk 0 (128x32)
#pragma unroll
        for (int p = 0; p < 2; p++) {
            int e = (tid + p * 256) * 8;
            int r = e >> 5, c = e & 31;
            cp_async16(smem_u32(&k_s[0][r * 40 + c]),
                       &g_kT[((size_t)b * NPIX + r) * 32 + c]);
        }
        cp_commit();
    }
    __syncthreads();

    uint32_t qa[2][4];
#pragma unroll
    for (int ks = 0; ks < 2; ks++) {
        int row = 16 * mw + (lane & 15);
        int col = 16 * ks + ((lane >= 16) ? 8 : 0);
        ldm_x4(qa[ks], smem_u32(&q_s[row * 40 + col]));
    }

    float mx0 = -1e30f, mx1 = -1e30f;
    const int NCH = NPIX / 128;  // 32
#pragma unroll 1
    for (int kc = 0; kc < NCH; kc++) {
        int buf = kc & 1;
        cp_wait<0>();
        __syncthreads();
        if (kc + 1 < NCH) {
#pragma unroll
            for (int p = 0; p < 2; p++) {
                int e = (tid + p * 256) * 8;
                int r = e >> 5, c = e & 31;
                cp_async16(smem_u32(&k_s[buf ^ 1][r * 40 + c]),
                           &g_kT[((size_t)b * NPIX + (kc + 1) * 128 + r) * 32 + c]);
            }
            cp_commit();
        }
        float sacc[8][4];
#pragma unroll
        for (int i = 0; i < 8; i++)
#pragma unroll
            for (int j = 0; j < 4; j++) sacc[i][j] = 0.f;
#pragma unroll
        for (int ks = 0; ks < 2; ks++) {
#pragma unroll
            for (int nbp = 0; nbp < 4; nbp++) {
                uint32_t bf[4];
                int key = nh * 64 + nbp * 16 + (lane & 7) + ((lane >= 16) ? 8 : 0);
                int col = 16 * ks + ((lane & 8) ? 8 : 0);
                ldm_x4(bf, smem_u32(&k_s[buf][key * 40 + col]));
                mma_16816(sacc[2 * nbp],     qa[ks], bf[0], bf[1]);
                mma_16816(sacc[2 * nbp + 1], qa[ks], bf[2], bf[3]);
            }
        }
#pragma unroll
        for (int j = 0; j < 8; j++) {
            mx0 = fmaxf(mx0, fmaxf(sacc[j][0], sacc[j][1]));
            mx1 = fmaxf(mx1, fmaxf(sacc[j][2], sacc[j][3]));
        }
    }
    // quad reduce (over t4 = key quarters)
#pragma unroll
    for (int off = 1; off < 4; off <<= 1) {
        mx0 = fmaxf(mx0, __shfl_xor_sync(0xffffffffu, mx0, off));
        mx1 = fmaxf(mx1, __shfl_xor_sync(0xffffffffu, mx1, off));
    }
    if ((lane & 3) == 0) {
        partial[nh][16 * mw + g]     = mx0;
        partial[nh][16 * mw + g + 8] = mx1;
    }
    __syncthreads();
    if (tid < 64)
        g_rowmax[(size_t)b * NPIX + nq0 + tid] = fmaxf(partial[0][tid], partial[1][tid]);
}

// ---------------- flash attention (two-pass: fixed max, no online rescale) ----------------
#define CK   64                        // keys per chunk
#define CCH  128                       // channels per CTA
#define VSTR 136                       // smem halves per V row (128 + 8 pad)
#define KTILE_B (CK * 40 * 2)          // 5120
#define VTILE_B (CK * VSTR * 2)        // 17408
#define OFF_Q 0
#define OFF_K 5120                     // 2 buffers
#define OFF_V (OFF_K + 2 * KTILE_B)    // 15360, 2 buffers
#define SMEM_TOTAL (OFF_V + 2 * VTILE_B)  // 50176
#define ONES_H2 0x3C003C00u

__device__ __forceinline__ void flash_load_chunk(char* smem_raw, int buf, int b, int j0,
                                                 int ch0, int tid) {
    __half* k_s = (__half*)(smem_raw + OFF_K + buf * KTILE_B);
    __half* v_s = (__half*)(smem_raw + OFF_V + buf * VTILE_B);
    {   // K chunk 64x32
        int e = tid * 8;
        int r = e >> 5, c = e & 31;
        cp_async16(smem_u32(&k_s[r * 40 + c]),
                   &g_kT[((size_t)b * NPIX + j0 + r) * 32 + c]);
    }
#pragma unroll
    for (int p = 0; p < 4; p++) {  // V chunk 64x128
        int e = (tid + p * 256) * 8;
        int r = e >> 7, c = e & 127;
        cp_async16(smem_u32(&v_s[r * VSTR + c]),
                   &g_vT[((size_t)b * NPIX + j0 + r) * NC + ch0 + c]);
    }
}

__global__ __launch_bounds__(256, 2) void flash_kernel(float* __restrict__ out) {
    extern __shared__ char smem_raw[];
    __half* q_s = (__half*)(smem_raw + OFF_Q);

    int nq0 = blockIdx.x * 64;
    int b   = blockIdx.y;
    int ch0 = blockIdx.z * CCH;
    int tid = threadIdx.x;
    int w = tid >> 5, lane = tid & 31, g = lane >> 2, t4 = lane & 3;
    int mw = w & 3;       // query row group: rows [16*mw, 16*mw+16)
    int nh = w >> 2;      // channel quarter for PV: chans ch0 + [64*nh, +64)

    {   // load Q tile (64x32)
        int e = tid * 8;
        int r = e >> 5, c = e & 31;
        *(uint4*)&q_s[r * 40 + c] = *(const uint4*)&g_qT[((size_t)b * NPIX + nq0 + r) * 32 + c];
    }

    // prefetch chunk 0
    flash_load_chunk(smem_raw, 0, b, 0, ch0, tid);
    cp_commit();

    // per-row fixed maxima (exact by construction)
    float mr0 = g_rowmax[(size_t)b * NPIX + nq0 + 16 * mw + g];
    float mr1 = g_rowmax[(size_t)b * NPIX + nq0 + 16 * mw + g + 8];

    float acc[8][4];
#pragma unroll
    for (int i = 0; i < 8; i++)
#pragma unroll
        for (int j = 0; j < 4; j++) acc[i][j] = 0.f;
    float lacc[4] = {0.f, 0.f, 0.f, 0.f};

    __syncthreads();  // Q visible
    uint32_t qa[2][4];
#pragma unroll
    for (int ks = 0; ks < 2; ks++) {
        int row = 16 * mw + (lane & 15);
        int col = 16 * ks + ((lane >= 16) ? 8 : 0);
        ldm_x4(qa[ks], smem_u32(&q_s[row * 40 + col]));
    }

    const int NCHUNK = NPIX / CK;  // 64
#pragma unroll 1
    for (int kc = 0; kc < NCHUNK; kc++) {
        int buf = kc & 1;
        cp_wait<0>();
        __syncthreads();  // chunk kc visible; all warps done reading buf^1
        if (kc + 1 < NCHUNK) {
            flash_load_chunk(smem_raw, buf ^ 1, b, (kc + 1) * CK, ch0, tid);
            cp_commit();
        }

        __half* k_s = (__half*)(smem_raw + OFF_K + buf * KTILE_B);
        __half* v_s = (__half*)(smem_raw + OFF_V + buf * VTILE_B);

        // ---- S' = Q' K^T (log2 domain): 16 rows x 64 keys, in registers ----
        float sacc[8][4];
#pragma unroll
        for (int i = 0; i < 8; i++)
#pragma unroll
            for (int j = 0; j < 4; j++) sacc[i][j] = 0.f;
#pragma unroll
        for (int ks = 0; ks < 2; ks++) {
#pragma unroll
            for (int nbp = 0; nbp < 4; nbp++) {
                uint32_t bf[4];
                int key = nbp * 16 + (lane & 7) + ((lane >= 16) ? 8 : 0);
                int col = 16 * ks + ((lane & 8) ? 8 : 0);
                ldm_x4(bf, smem_u32(&k_s[key * 40 + col]));
                mma_16816(sacc[2 * nbp],     qa[ks], bf[0], bf[1]);
                mma_16816(sacc[2 * nbp + 1], qa[ks], bf[2], bf[3]);
            }
        }

        // ---- P = 2^(s - m): straight to packed fp16 A-fragments ----
        uint32_t pa[4][4];
#pragma unroll
        for (int ks = 0; ks < 4; ks++) {
            pa[ks][0] = h2exp2(h2_as_u32(__floats2half2_rn(sacc[2 * ks][0] - mr0,     sacc[2 * ks][1] - mr0)));
            pa[ks][1] = h2exp2(h2_as_u32(__floats2half2_rn(sacc[2 * ks][2] - mr1,     sacc[2 * ks][3] - mr1)));
            pa[ks][2] = h2exp2(h2_as_u32(__floats2half2_rn(sacc[2 * ks + 1][0] - mr0, sacc[2 * ks + 1][1] - mr0)));
            pa[ks][3] = h2exp2(h2_as_u32(__floats2half2_rn(sacc[2 * ks + 1][2] - mr1, sacc[2 * ks + 1][3] - mr1)));
        }

        // ---- O += P V : 16 rows x 64 channels ----
#pragma unroll
        for (int ks = 0; ks < 4; ks++) {
#pragma unroll
            for (int nbp = 0; nbp < 4; nbp++) {
                uint32_t bf[4];
                int key  = 16 * ks + (lane & 15);
                int chan = nh * 64 + 16 * nbp + ((lane >= 16) ? 8 : 0);
                ldm_x4_t(bf, smem_u32(&v_s[key * VSTR + chan]));
                mma_16816(acc[2 * nbp],     pa[ks], bf[0], bf[1]);
                mma_16816(acc[2 * nbp + 1], pa[ks], bf[2], bf[3]);
            }
        }
        // ---- l += P . 1 (row sums via tensor core) ----
#pragma unroll
        for (int ks = 0; ks < 4; ks++)
            mma_16816(lacc, pa[ks], ONES_H2, ONES_H2);
    }

    float l0 = lacc[0], l1 = lacc[2];

    // ---- finalize: divide by l, stage transposed, coalesced write ----
    __syncthreads();
    float* o_s = (float*)smem_raw;  // [64][132] float = 33792 B, reuses buffers
    {
        int ra = 16 * mw + g;
        float inv0 = 1.f / l0;
        float inv1 = 1.f / l1;
#pragma unroll
        for (int nt = 0; nt < 8; nt++) {
            int col = nh * 64 + 8 * nt + 2 * t4;
            o_s[ra * 132 + col]           = acc[nt][0] * inv0;
            o_s[ra * 132 + col + 1]       = acc[nt][1] * inv0;
            o_s[(ra + 8) * 132 + col]     = acc[nt][2] * inv1;
            o_s[(ra + 8) * 132 + col + 1] = acc[nt][3] * inv1;
        }
    }
    __syncthreads();
    int nl = tid & 63;
    int cb = tid >> 6;  // 0..3
#pragma unroll
    for (int it = 0; it < 32; it++) {
        int c = it * 4 + cb;
        out[((size_t)b * NC + ch0 + c) * NPIX + nq0 + nl] = o_s[nl * 132 + c];
    }
}

// ---------------- launcher ----------------
extern "C" void kernel_launch(void* const* d_in, const int* in_sizes, int n_in,
                              void* d_out, int out_size) {
    (void)in_sizes; (void)n_in; (void)out_size;
    const float* x  = (const float*)d_in[0];
    const float* wq = (const float*)d_in[1];
    const float* bq = (const float*)d_in[2];
    const float* wk = (const float*)d_in[3];
    const float* bk = (const float*)d_in[4];
    const float* wv = (const float*)d_in[5];
    const float* bv = (const float*)d_in[6];
    float* out = (float*)d_out;

    pack_w_kernel<<<(MR * NC + 255) / 256, 256>>>(wq, wk, wv);
    pack_x_kernel<<<(NB * NC * NPIX / 4 + 255) / 256, 256>>>(x);

    dim3 pg(NPIX / 64, MR / 64, NB);
    proj_kernel<<<pg, 128>>>(bq, bk, bv);

    dim3 mg(NPIX / 64, NB);
    qk_max_kernel<<<mg, 256>>>();

    cudaFuncSetAttribute(flash_kernel, cudaFuncAttributeMaxDynamicSharedMemorySize, SMEM_TOTAL);
    dim3 fg(NPIX / 64, NB, NC / CCH);
    flash_kernel<<<fg, 256, SMEM_TOTAL>>>(out);
}

// round 10
// speedup vs baseline: 1.1159x; 1.1159x over previous
#include <cuda_runtime.h>
#include <cuda_fp16.h>
#include <stdint.h>

#define NB   8
#define NC   256
#define NPIX 4096
#define KST  768      // stacked K: [x_h; x_l; x_h(reused)]
#define KSL  512      // stored slabs (hi, lo)
#define MR   320      // 32 q + 32 k + 256 v output channels
#define LOG2E 1.4426950408889634f

// ---------------- scratch (device globals; no allocation) ----------------
__device__ __half g_xs[(size_t)NB * KSL * NPIX];   // stacked x (fp16 hi/lo)
__device__ __half g_ws[MR * KST];                  // stacked weights
__device__ __half g_qT[(size_t)NB * NPIX * 32];    // [b][n][d] (q pre-scaled by log2e)
__device__ __half g_kT[(size_t)NB * NPIX * 32];    // [b][n][d]
__device__ __half g_vT[(size_t)NB * NPIX * NC];    // [b][n][c]

// ---------------- mma / ldmatrix / cp.async helpers ----------------
__device__ __forceinline__ unsigned smem_u32(const void* p) {
    return (unsigned)__cvta_generic_to_shared(p);
}
__device__ __forceinline__ uint32_t h2_as_u32(__half2 h) {
    return *reinterpret_cast<uint32_t*>(&h);
}
__device__ __forceinline__ uint32_t h2exp2(uint32_t x) {
    uint32_t r;
    asm("ex2.approx.f16x2 %0, %1;" : "=r"(r) : "r"(x));
    return r;
}
__device__ __forceinline__ float ex2f(float x) {
    float r;
    asm("ex2.approx.f32 %0, %1;" : "=f"(r) : "f"(x));
    return r;
}
__device__ __forceinline__ void ldm_x4(uint32_t* r, unsigned addr) {
    asm volatile("ldmatrix.sync.aligned.m8n8.x4.shared.b16 {%0,%1,%2,%3}, [%4];\n"
                 : "=r"(r[0]), "=r"(r[1]), "=r"(r[2]), "=r"(r[3]) : "r"(addr));
}
__device__ __forceinline__ void ldm_x4_t(uint32_t* r, unsigned addr) {
    asm volatile("ldmatrix.sync.aligned.m8n8.x4.trans.shared.b16 {%0,%1,%2,%3}, [%4];\n"
                 : "=r"(r[0]), "=r"(r[1]), "=r"(r[2]), "=r"(r[3]) : "r"(addr));
}
__device__ __forceinline__ void mma_16816(float* d, const uint32_t* a, uint32_t b0, uint32_t b1) {
    asm volatile(
        "mma.sync.aligned.m16n8k16.row.col.f32.f16.f16.f32 "
        "{%0,%1,%2,%3},{%4,%5,%6,%7},{%8,%9},{%0,%1,%2,%3};\n"
        : "+f"(d[0]), "+f"(d[1]), "+f"(d[2]), "+f"(d[3])
        : "r"(a[0]), "r"(a[1]), "r"(a[2]), "r"(a[3]), "r"(b0), "r"(b1));
}
__device__ __forceinline__ void cp_async16(unsigned dst, const void* src) {
    asm volatile("cp.async.cg.shared.global [%0], [%1], 16;\n" :: "r"(dst), "l"(src));
}
__device__ __forceinline__ void cp_commit() {
    asm volatile("cp.async.commit_group;\n");
}
template <int N>
__device__ __forceinline__ void cp_wait() {
    asm volatile("cp.async.wait_group %0;\n" :: "n"(N));
}

// ---------------- pack kernels ----------------
__global__ void pack_w_kernel(const float* __restrict__ wq, const float* __restrict__ wk,
                              const float* __restrict__ wv) {
    int idx = blockIdx.x * blockDim.x + threadIdx.x;
    if (idx >= MR * NC) return;
    int k = idx & 255;
    int m = idx >> 8;
    float w = (m < 32) ? wq[m * NC + k] * LOG2E
            : (m < 64) ? wk[(m - 32) * NC + k]
                       : wv[(m - 64) * NC + k];
    __half hi = __float2half_rn(w);
    __half lo = __float2half_rn(w - __half2float(hi));
    g_ws[m * KST + k]       = hi;
    g_ws[m * KST + 256 + k] = hi;
    g_ws[m * KST + 512 + k] = lo;
}

__global__ void pack_x_kernel(const float* __restrict__ x) {
    int idx = blockIdx.x * blockDim.x + threadIdx.x;
    const int total = NB * NC * NPIX / 4;
    if (idx >= total) return;
    float4 v = ((const float4*)x)[idx];
    int n4 = idx % (NPIX / 4);
    int t  = idx / (NPIX / 4);
    int c  = t % NC;
    int b  = t / NC;
    float f[4] = {v.x, v.y, v.z, v.w};
    __align__(8) __half hi[4], lo[4];
#pragma unroll
    for (int i = 0; i < 4; i++) {
        hi[i] = __float2half_rn(f[i]);
        lo[i] = __float2half_rn(f[i] - __half2float(hi[i]));
    }
    size_t base = ((size_t)b * KSL) * NPIX + (size_t)n4 * 4;
    *(uint2*)&g_xs[base + (size_t)c * NPIX]         = *(uint2*)&hi[0];
    *(uint2*)&g_xs[base + (size_t)(c + 256) * NPIX] = *(uint2*)&lo[0];
}

// ---------------- projection GEMM: C[320,4096] = Ws[320,768] * Xs[768,4096] ----------------
#define PA_STR 40
#define PB_STR 72

__global__ __launch_bounds__(128) void proj_kernel(const float* __restrict__ bq,
                                                   const float* __restrict__ bk,
                                                   const float* __restrict__ bv) {
    __shared__ __half a_s[64 * PA_STR];
    __shared__ __half b_s[32 * PB_STR];
    __shared__ __half c_s[64 * PB_STR];

    int n0 = blockIdx.x * 64;
    int m0 = blockIdx.y * 64;
    int b  = blockIdx.z;
    int tid = threadIdx.x;
    int w = tid >> 5, lane = tid & 31;
    int g = lane >> 2, t4 = lane & 3;

    float acc[8][4];
#pragma unroll
    for (int i = 0; i < 8; i++)
#pragma unroll
        for (int j = 0; j < 4; j++) acc[i][j] = 0.f;

    const __half* gA = &g_ws[m0 * KST];
    const __half* gB = &g_xs[(size_t)b * KSL * NPIX + n0];

    for (int kt = 0; kt < KST / 32; kt++) {
        int k0 = kt * 32;
        int kk = (k0 < KSL) ? k0 : (k0 - KSL);
        __syncthreads();
#pragma unroll
        for (int p = 0; p < 2; p++) {
            int e = (tid + p * 128) * 8;
            int r = e >> 5, c = e & 31;
            *(uint4*)&a_s[r * PA_STR + c] = *(const uint4*)&gA[r * KST + k0 + c];
        }
#pragma unroll
        for (int p = 0; p < 2; p++) {
            int e = (tid + p * 128) * 8;
            int r = e >> 6, c = e & 63;
            *(uint4*)&b_s[r * PB_STR + c] = *(const uint4*)&gB[(size_t)(kk + r) * NPIX + c];
        }
        __syncthreads();
#pragma unroll
        for (int ks = 0; ks < 2; ks++) {
            uint32_t af[4];
            {
                int row = 16 * w + (lane & 15);
                int col = 16 * ks + ((lane >= 16) ? 8 : 0);
                ldm_x4(af, smem_u32(&a_s[row * PA_STR + col]));
            }
#pragma unroll
            for (int nbp = 0; nbp < 4; nbp++) {
                uint32_t bf[4];
                int row = 16 * ks + (lane & 15);
                int col = 16 * nbp + ((lane >= 16) ? 8 : 0);
                ldm_x4_t(bf, smem_u32(&b_s[row * PB_STR + col]));
                mma_16816(acc[2 * nbp],     af, bf[0], bf[1]);
                mma_16816(acc[2 * nbp + 1], af, bf[2], bf[3]);
            }
        }
    }
    __syncthreads();
    int row_a = 16 * w + g;
    int row_b = row_a + 8;
    int ma = m0 + row_a, mb = m0 + row_b;
    float bias_a = (ma < 32) ? bq[ma] * LOG2E : (ma < 64) ? bk[ma - 32] : bv[ma - 64];
    float bias_b = (mb < 32) ? bq[mb] * LOG2E : (mb < 64) ? bk[mb - 32] : bv[mb - 64];
#pragma unroll
    for (int nt = 0; nt < 8; nt++) {
        int col = 8 * nt + 2 * t4;
        c_s[row_a * PB_STR + col]     = __float2half_rn(acc[nt][0] + bias_a);
        c_s[row_a * PB_STR + col + 1] = __float2half_rn(acc[nt][1] + bias_a);
        c_s[row_b * PB_STR + col]     = __float2half_rn(acc[nt][2] + bias_b);
        c_s[row_b * PB_STR + col + 1] = __float2half_rn(acc[nt][3] + bias_b);
    }
    __syncthreads();
    // transposed coalesced writeback
    int n = tid & 63, part = tid >> 6;
    __align__(16) __half tmp[32];
#pragma unroll
    for (int j = 0; j < 32; j++) tmp[j] = c_s[(part * 32 + j) * PB_STR + n];
    int ng = n0 + n;
    __half* dst;
    if (m0 == 0) {
        dst = (part == 0) ? &g_qT[((size_t)b * NPIX + ng) * 32]
                          : &g_kT[((size_t)b * NPIX + ng) * 32];
    } else {
        int cb = (m0 - 64) + part * 32;
        dst = &g_vT[((size_t)b * NPIX + ng) * NC + cb];
    }
#pragma unroll
    for (int q = 0; q < 4; q++) ((uint4*)dst)[q] = ((uint4*)tmp)[q];
}

// ---------------- flash attention: 128 queries x 256 channels per CTA, 512 threads ----------------
#define CK   64                        // keys per load chunk (processed as 2x32)
#define VSTR 264                       // smem halves per V row (256 + 8 pad)
#define KTILE_B (CK * 40 * 2)          // 5120
#define VTILE_B (CK * VSTR * 2)        // 33792
#define OFF_Q 0                        // 128 x 40 halfs = 10240 B
#define OFF_K 10240                    // 3 stages
#define OFF_V (OFF_K + 3 * KTILE_B)    // 25600, 3 stages
#define SMEM_TOTAL (OFF_V + 3 * VTILE_B)  // 126976
#define ONES_H2 0x3C003C00u

__device__ __forceinline__ void flash_load_chunk(uint32_t smem_base, int buf, int b, int j0,
                                                 int tid) {
    if (tid < 256) {   // K chunk 64x32
        int e = tid * 8;
        int r = e >> 5, c = e & 31;
        cp_async16(smem_base + OFF_K + buf * KTILE_B + (r * 40 + c) * 2,
                   &g_kT[((size_t)b * NPIX + j0 + r) * 32 + c]);
    }
#pragma unroll
    for (int p = 0; p < 4; p++) {  // V chunk 64x256
        int e = (tid + p * 512) * 8;
        int r = e >> 8, c = e & 255;
        cp_async16(smem_base + OFF_V + buf * VTILE_B + (r * VSTR + c) * 2,
                   &g_vT[((size_t)b * NPIX + j0 + r) * NC + c]);
    }
}

__global__ __launch_bounds__(512, 1) void flash_kernel(float* __restrict__ out) {
    extern __shared__ char smem_raw[];
    uint32_t smem_base = smem_u32(smem_raw);
    __half* q_s = (__half*)(smem_raw + OFF_Q);

    int nq0 = blockIdx.x * 128;
    int b   = blockIdx.y;
    int tid = threadIdx.x;
    int w = tid >> 5, lane = tid & 31, g = lane >> 2, t4 = lane & 3;
    int mw = w & 7;       // query row group: rows [16*mw, 16*mw+16)
    int nh = w >> 3;      // channel half for PV: chans [128*nh, +128)

    {   // load Q tile (128x32)
        int e = tid * 8;
        int r = e >> 5, c = e & 31;
        *(uint4*)&q_s[r * 40 + c] = *(const uint4*)&g_qT[((size_t)b * NPIX + nq0 + r) * 32 + c];
    }

    // prefetch chunks 0, 1
    flash_load_chunk(smem_base, 0, b, 0, tid); cp_commit();
    flash_load_chunk(smem_base, 1, b, CK, tid); cp_commit();

    float acc[16][4];
#pragma unroll
    for (int i = 0; i < 16; i++)
#pragma unroll
        for (int j = 0; j < 4; j++) acc[i][j] = 0.f;
    float lacc[4] = {0.f, 0.f, 0.f, 0.f};
    float m0 = -1e30f, m1 = -1e30f;

    __syncthreads();  // Q visible
    uint32_t qa[2][4];
#pragma unroll
    for (int ks = 0; ks < 2; ks++) {
        int row = 16 * mw + (lane & 15);
        int col = 16 * ks + ((lane >= 16) ? 8 : 0);
        ldm_x4(qa[ks], smem_u32(&q_s[row * 40 + col]));
    }

    const int NCHUNK = NPIX / CK;  // 64
#pragma unroll 1
    for (int kc = 0; kc < NCHUNK; kc++) {
        int buf = kc % 3;
        if (kc + 1 < NCHUNK) cp_wait<1>(); else cp_wait<0>();
        __syncthreads();  // chunk kc visible; all warps done with chunk kc-1
        if (kc + 2 < NCHUNK) {
            flash_load_chunk(smem_base, (kc + 2) % 3, b, (kc + 2) * CK, tid);
            cp_commit();
        }

        __half* k_s = (__half*)(smem_raw + OFF_K + buf * KTILE_B);
        __half* v_s = (__half*)(smem_raw + OFF_V + buf * VTILE_B);

#pragma unroll
        for (int s = 0; s < 2; s++) {   // 32-key sub-chunks
            // ---- S' = Q' K^T (log2 domain): 16 rows x 32 keys ----
            float sacc[4][4];
#pragma unroll
            for (int i = 0; i < 4; i++)
#pragma unroll
                for (int j = 0; j < 4; j++) sacc[i][j] = 0.f;
#pragma unroll
            for (int ks = 0; ks < 2; ks++) {
#pragma unroll
                for (int nbp = 0; nbp < 2; nbp++) {
                    uint32_t bf[4];
                    int key = 32 * s + nbp * 16 + (lane & 7) + ((lane >= 16) ? 8 : 0);
                    int col = 16 * ks + ((lane & 8) ? 8 : 0);
                    ldm_x4(bf, smem_u32(&k_s[key * 40 + col]));
                    mma_16816(sacc[2 * nbp],     qa[ks], bf[0], bf[1]);
                    mma_16816(sacc[2 * nbp + 1], qa[ks], bf[2], bf[3]);
                }
            }

            // ---- online softmax (base-2) ----
            float mx0 = sacc[0][0], mx1 = sacc[0][2];
#pragma unroll
            for (int j = 0; j < 4; j++) {
                mx0 = fmaxf(mx0, fmaxf(sacc[j][0], sacc[j][1]));
                mx1 = fmaxf(mx1, fmaxf(sacc[j][2], sacc[j][3]));
            }
#pragma unroll
            for (int off = 1; off < 4; off <<= 1) {
                mx0 = fmaxf(mx0, __shfl_xor_sync(0xffffffffu, mx0, off));
                mx1 = fmaxf(mx1, __shfl_xor_sync(0xffffffffu, mx1, off));
            }
            float mn0 = fmaxf(m0, mx0), mn1 = fmaxf(m1, mx1);
            float al0 = ex2f(m0 - mn0), al1 = ex2f(m1 - mn1);
            m0 = mn0; m1 = mn1;

            // P fragments via f16x2 ex2
            uint32_t pa[2][4];
#pragma unroll
            for (int t = 0; t < 2; t++) {
                pa[t][0] = h2exp2(h2_as_u32(__floats2half2_rn(sacc[2 * t][0] - mn0,     sacc[2 * t][1] - mn0)));
                pa[t][1] = h2exp2(h2_as_u32(__floats2half2_rn(sacc[2 * t][2] - mn1,     sacc[2 * t][3] - mn1)));
                pa[t][2] = h2exp2(h2_as_u32(__floats2half2_rn(sacc[2 * t + 1][0] - mn0, sacc[2 * t + 1][1] - mn0)));
                pa[t][3] = h2exp2(h2_as_u32(__floats2half2_rn(sacc[2 * t + 1][2] - mn1, sacc[2 * t + 1][3] - mn1)));
            }

            // rescale O and l accumulators
#pragma unroll
            for (int nt = 0; nt < 16; nt++) {
                acc[nt][0] *= al0; acc[nt][1] *= al0;
                acc[nt][2] *= al1; acc[nt][3] *= al1;
            }
            lacc[0] *= al0; lacc[1] *= al0; lacc[2] *= al1; lacc[3] *= al1;

            // ---- O += P V : 16 rows x 128 channels ----
#pragma unroll
            for (int t = 0; t < 2; t++) {
#pragma unroll
                for (int nbp = 0; nbp < 8; nbp++) {
                    uint32_t bf[4];
                    int key  = 32 * s + 16 * t + (lane & 15);
                    int chan = nh * 128 + 16 * nbp + ((lane >= 16) ? 8 : 0);
                    ldm_x4_t(bf, smem_u32(&v_s[key * VSTR + chan]));
                    mma_16816(acc[2 * nbp],     pa[t], bf[0], bf[1]);
                    mma_16816(acc[2 * nbp + 1], pa[t], bf[2], bf[3]);
                }
                mma_16816(lacc, pa[t], ONES_H2, ONES_H2);
            }
        }
    }

    // ---- finalize: divide by l, direct fragment writeback ----
    float inv0 = 1.f / lacc[0];
    float inv1 = 1.f / lacc[2];
    int r0 = nq0 + 16 * mw + g;
    int r1 = r0 + 8;
#pragma unroll
    for (int nt = 0; nt < 16; nt++) {
        int c = nh * 128 + 8 * nt + 2 * t4;
        size_t base0 = ((size_t)b * NC + c) * NPIX;
        size_t base1 = ((size_t)b * NC + c + 1) * NPIX;
        out[base0 + r0] = acc[nt][0] * inv0;
        out[base1 + r0] = acc[nt][1] * inv0;
        out[base0 + r1] = acc[nt][2] * inv1;
        out[base1 + r1] = acc[nt][3] * inv1;
    }
}

// ---------------- launcher ----------------
extern "C" void kernel_launch(void* const* d_in, const int* in_sizes, int n_in,
                              void* d_out, int out_size) {
    (void)in_sizes; (void)n_in; (void)out_size;
    const float* x  = (const float*)d_in[0];
    const float* wq = (const float*)d_in[1];
    const float* bq = (const float*)d_in[2];
    const float* wk = (const float*)d_in[3];
    const float* bk = (const float*)d_in[4];
    const float* wv = (const float*)d_in[5];
    const float* bv = (const float*)d_in[6];
    float* out = (float*)d_out;

    pack_w_kernel<<<(MR * NC + 255) / 256, 256>>>(wq, wk, wv);
    pack_x_kernel<<<(NB * NC * NPIX / 4 + 255) / 256, 256>>>(x);

    dim3 pg(NPIX / 64, MR / 64, NB);
    proj_kernel<<<pg, 128>>>(bq, bk, bv);

    cudaFuncSetAttribute(flash_kernel, cudaFuncAttributeMaxDynamicSharedMemorySize, SMEM_TOTAL);
    dim3 fg(NPIX / 128, NB);
    flash_kernel<<<fg, 512, SMEM_TOTAL>>>(out);
}

// round 11
// speedup vs baseline: 1.1610x; 1.0405x over previous
#include <cuda_runtime.h>
#include <cuda_fp16.h>
#include <stdint.h>

#define NB   8
#define NC   256
#define NPIX 4096
#define KST  768      // stacked K: [x_h; x_l; x_h(reused)]
#define KSL  512      // stored slabs (hi, lo)
#define MR   320      // 32 q + 32 k + 256 v output channels
#define LOG2E 1.4426950408889634f

// ---------------- scratch (device globals; no allocation) ----------------
__device__ __half g_xs[(size_t)NB * KSL * NPIX];   // stacked x (fp16 hi/lo)
__device__ __half g_ws[MR * KST];                  // stacked weights
__device__ __half g_qT[(size_t)NB * NPIX * 32];    // [b][n][d] (q pre-scaled by log2e)
__device__ __half g_kT[(size_t)NB * NPIX * 32];    // [b][n][d]
__device__ __half g_vT[(size_t)NB * NPIX * NC];    // [b][n][c]

// ---------------- mma / ldmatrix / cp.async helpers ----------------
__device__ __forceinline__ unsigned smem_u32(const void* p) {
    return (unsigned)__cvta_generic_to_shared(p);
}
__device__ __forceinline__ uint32_t h2_as_u32(__half2 h) {
    return *reinterpret_cast<uint32_t*>(&h);
}
__device__ __forceinline__ uint32_t h2exp2(uint32_t x) {
    uint32_t r;
    asm("ex2.approx.f16x2 %0, %1;" : "=r"(r) : "r"(x));
    return r;
}
__device__ __forceinline__ float ex2f(float x) {
    float r;
    asm("ex2.approx.f32 %0, %1;" : "=f"(r) : "f"(x));
    return r;
}
__device__ __forceinline__ void ldm_x4(uint32_t* r, unsigned addr) {
    asm volatile("ldmatrix.sync.aligned.m8n8.x4.shared.b16 {%0,%1,%2,%3}, [%4];\n"
                 : "=r"(r[0]), "=r"(r[1]), "=r"(r[2]), "=r"(r[3]) : "r"(addr));
}
__device__ __forceinline__ void ldm_x4_t(uint32_t* r, unsigned addr) {
    asm volatile("ldmatrix.sync.aligned.m8n8.x4.trans.shared.b16 {%0,%1,%2,%3}, [%4];\n"
                 : "=r"(r[0]), "=r"(r[1]), "=r"(r[2]), "=r"(r[3]) : "r"(addr));
}
__device__ __forceinline__ void mma_16816(float* d, const uint32_t* a, uint32_t b0, uint32_t b1) {
    asm volatile(
        "mma.sync.aligned.m16n8k16.row.col.f32.f16.f16.f32 "
        "{%0,%1,%2,%3},{%4,%5,%6,%7},{%8,%9},{%0,%1,%2,%3};\n"
        : "+f"(d[0]), "+f"(d[1]), "+f"(d[2]), "+f"(d[3])
        : "r"(a[0]), "r"(a[1]), "r"(a[2]), "r"(a[3]), "r"(b0), "r"(b1));
}
__device__ __forceinline__ void cp_async16(unsigned dst, const void* src) {
    asm volatile("cp.async.cg.shared.global [%0], [%1], 16;\n" :: "r"(dst), "l"(src));
}
__device__ __forceinline__ void cp_commit() {
    asm volatile("cp.async.commit_group;\n");
}
template <int N>
__device__ __forceinline__ void cp_wait() {
    asm volatile("cp.async.wait_group %0;\n" :: "n"(N));
}

// ---------------- pack kernels ----------------
__global__ void pack_w_kernel(const float* __restrict__ wq, const float* __restrict__ wk,
                              const float* __restrict__ wv) {
    int idx = blockIdx.x * blockDim.x + threadIdx.x;
    if (idx >= MR * NC) return;
    int k = idx & 255;
    int m = idx >> 8;
    float w = (m < 32) ? wq[m * NC + k] * LOG2E
            : (m < 64) ? wk[(m - 32) * NC + k]
                       : wv[(m - 64) * NC + k];
    __half hi = __float2half_rn(w);
    __half lo = __float2half_rn(w - __half2float(hi));
    g_ws[m * KST + k]       = hi;
    g_ws[m * KST + 256 + k] = hi;
    g_ws[m * KST + 512 + k] = lo;
}

__global__ void pack_x_kernel(const float* __restrict__ x) {
    int idx = blockIdx.x * blockDim.x + threadIdx.x;
    const int total = NB * NC * NPIX / 4;
    if (idx >= total) return;
    float4 v = ((const float4*)x)[idx];
    int n4 = idx % (NPIX / 4);
    int t  = idx / (NPIX / 4);
    int c  = t % NC;
    int b  = t / NC;
    float f[4] = {v.x, v.y, v.z, v.w};
    __align__(8) __half hi[4], lo[4];
#pragma unroll
    for (int i = 0; i < 4; i++) {
        hi[i] = __float2half_rn(f[i]);
        lo[i] = __float2half_rn(f[i] - __half2float(hi[i]));
    }
    size_t base = ((size_t)b * KSL) * NPIX + (size_t)n4 * 4;
    *(uint2*)&g_xs[base + (size_t)c * NPIX]         = *(uint2*)&hi[0];
    *(uint2*)&g_xs[base + (size_t)(c + 256) * NPIX] = *(uint2*)&lo[0];
}

// ---------------- projection GEMM: C[320,4096] = Ws[320,768] * Xs[768,4096] ----------------
#define PA_STR 40
#define PB_STR 72

__global__ __launch_bounds__(128) void proj_kernel(const float* __restrict__ bq,
                                                   const float* __restrict__ bk,
                                                   const float* __restrict__ bv) {
    __shared__ __half a_s[64 * PA_STR];
    __shared__ __half b_s[32 * PB_STR];
    __shared__ __half c_s[64 * PB_STR];

    int n0 = blockIdx.x * 64;
    int m0 = blockIdx.y * 64;
    int b  = blockIdx.z;
    int tid = threadIdx.x;
    int w = tid >> 5, lane = tid & 31;
    int g = lane >> 2, t4 = lane & 3;

    float acc[8][4];
#pragma unroll
    for (int i = 0; i < 8; i++)
#pragma unroll
        for (int j = 0; j < 4; j++) acc[i][j] = 0.f;

    const __half* gA = &g_ws[m0 * KST];
    const __half* gB = &g_xs[(size_t)b * KSL * NPIX + n0];

    for (int kt = 0; kt < KST / 32; kt++) {
        int k0 = kt * 32;
        int kk = (k0 < KSL) ? k0 : (k0 - KSL);
        __syncthreads();
#pragma unroll
        for (int p = 0; p < 2; p++) {
            int e = (tid + p * 128) * 8;
            int r = e >> 5, c = e & 31;
            *(uint4*)&a_s[r * PA_STR + c] = *(const uint4*)&gA[r * KST + k0 + c];
        }
#pragma unroll
        for (int p = 0; p < 2; p++) {
            int e = (tid + p * 128) * 8;
            int r = e >> 6, c = e & 63;
            *(uint4*)&b_s[r * PB_STR + c] = *(const uint4*)&gB[(size_t)(kk + r) * NPIX + c];
        }
        __syncthreads();
#pragma unroll
        for (int ks = 0; ks < 2; ks++) {
            uint32_t af[4];
            {
                int row = 16 * w + (lane & 15);
                int col = 16 * ks + ((lane >= 16) ? 8 : 0);
                ldm_x4(af, smem_u32(&a_s[row * PA_STR + col]));
            }
#pragma unroll
            for (int nbp = 0; nbp < 4; nbp++) {
                uint32_t bf[4];
                int row = 16 * ks + (lane & 15);
                int col = 16 * nbp + ((lane >= 16) ? 8 : 0);
                ldm_x4_t(bf, smem_u32(&b_s[row * PB_STR + col]));
                mma_16816(acc[2 * nbp],     af, bf[0], bf[1]);
                mma_16816(acc[2 * nbp + 1], af, bf[2], bf[3]);
            }
        }
    }
    __syncthreads();
    int row_a = 16 * w + g;
    int row_b = row_a + 8;
    int ma = m0 + row_a, mb = m0 + row_b;
    float bias_a = (ma < 32) ? bq[ma] * LOG2E : (ma < 64) ? bk[ma - 32] : bv[ma - 64];
    float bias_b = (mb < 32) ? bq[mb] * LOG2E : (mb < 64) ? bk[mb - 32] : bv[mb - 64];
#pragma unroll
    for (int nt = 0; nt < 8; nt++) {
        int col = 8 * nt + 2 * t4;
        c_s[row_a * PB_STR + col]     = __float2half_rn(acc[nt][0] + bias_a);
        c_s[row_a * PB_STR + col + 1] = __float2half_rn(acc[nt][1] + bias_a);
        c_s[row_b * PB_STR + col]     = __float2half_rn(acc[nt][2] + bias_b);
        c_s[row_b * PB_STR + col + 1] = __float2half_rn(acc[nt][3] + bias_b);
    }
    __syncthreads();
    // transposed coalesced writeback
    int n = tid & 63, part = tid >> 6;
    __align__(16) __half tmp[32];
#pragma unroll
    for (int j = 0; j < 32; j++) tmp[j] = c_s[(part * 32 + j) * PB_STR + n];
    int ng = n0 + n;
    __half* dst;
    if (m0 == 0) {
        dst = (part == 0) ? &g_qT[((size_t)b * NPIX + ng) * 32]
                          : &g_kT[((size_t)b * NPIX + ng) * 32];
    } else {
        int cb = (m0 - 64) + part * 32;
        dst = &g_vT[((size_t)b * NPIX + ng) * NC + cb];
    }
#pragma unroll
    for (int q = 0; q < 4; q++) ((uint4*)dst)[q] = ((uint4*)tmp)[q];
}

// ---------------- flash attention: 128 q x 256 ch per CTA, 512 thr, 128-key chunks ----------------
#define CK   128                       // keys per load chunk (processed as 4x32)
#define VSTR 264                       // smem halves per V row (256 + 8 pad)
#define KTILE_B (CK * 40 * 2)          // 10240
#define VTILE_B (CK * VSTR * 2)        // 67584
#define OFF_Q 0                        // 128 x 40 halfs = 10240 B
#define OFF_K 10240                    // 2 stages
#define OFF_V (OFF_K + 2 * KTILE_B)    // 30720, 2 stages
#define SMEM_TOTAL (OFF_V + 2 * VTILE_B)  // 165888
#define ONES_H2 0x3C003C00u

__device__ __forceinline__ void flash_load_chunk(uint32_t smem_base, int buf, int b, int j0,
                                                 int tid) {
    {   // K chunk 128x32 (all 512 threads)
        int e = tid * 8;
        int r = e >> 5, c = e & 31;
        cp_async16(smem_base + OFF_K + buf * KTILE_B + (r * 40 + c) * 2,
                   &g_kT[((size_t)b * NPIX + j0 + r) * 32 + c]);
    }
#pragma unroll
    for (int p = 0; p < 8; p++) {  // V chunk 128x256
        int e = (tid + p * 512) * 8;
        int r = e >> 8, c = e & 255;
        cp_async16(smem_base + OFF_V + buf * VTILE_B + (r * VSTR + c) * 2,
                   &g_vT[((size_t)b * NPIX + j0 + r) * NC + c]);
    }
}

__global__ __launch_bounds__(512, 1) void flash_kernel(float* __restrict__ out) {
    extern __shared__ char smem_raw[];
    uint32_t smem_base = smem_u32(smem_raw);
    __half* q_s = (__half*)(smem_raw + OFF_Q);

    int nq0 = blockIdx.x * 128;
    int b   = blockIdx.y;
    int tid = threadIdx.x;
    int w = tid >> 5, lane = tid & 31, g = lane >> 2, t4 = lane & 3;
    int mw = w & 7;       // query row group: rows [16*mw, 16*mw+16)
    int nh = w >> 3;      // channel half for PV: chans [128*nh, +128)

    {   // load Q tile (128x32)
        int e = tid * 8;
        int r = e >> 5, c = e & 31;
        *(uint4*)&q_s[r * 40 + c] = *(const uint4*)&g_qT[((size_t)b * NPIX + nq0 + r) * 32 + c];
    }

    // prefetch chunk 0
    flash_load_chunk(smem_base, 0, b, 0, tid);
    cp_commit();

    float acc[16][4];
#pragma unroll
    for (int i = 0; i < 16; i++)
#pragma unroll
        for (int j = 0; j < 4; j++) acc[i][j] = 0.f;
    float lacc[4] = {0.f, 0.f, 0.f, 0.f};
    float m0 = -1e30f, m1 = -1e30f;

    __syncthreads();  // Q visible
    uint32_t qa[2][4];
#pragma unroll
    for (int ks = 0; ks < 2; ks++) {
        int row = 16 * mw + (lane & 15);
        int col = 16 * ks + ((lane >= 16) ? 8 : 0);
        ldm_x4(qa[ks], smem_u32(&q_s[row * 40 + col]));
    }

    const int NCHUNK = NPIX / CK;  // 32
#pragma unroll 1
    for (int kc = 0; kc < NCHUNK; kc++) {
        int buf = kc & 1;
        cp_wait<0>();
        __syncthreads();  // chunk kc visible; all warps done reading buf^1
        if (kc + 1 < NCHUNK) {
            flash_load_chunk(smem_base, buf ^ 1, b, (kc + 1) * CK, tid);
            cp_commit();
        }

        __half* k_s = (__half*)(smem_raw + OFF_K + buf * KTILE_B);
        __half* v_s = (__half*)(smem_raw + OFF_V + buf * VTILE_B);

#pragma unroll
        for (int s = 0; s < 4; s++) {   // 32-key sub-chunks
            // ---- S' = Q' K^T (log2 domain): 16 rows x 32 keys ----
            float sacc[4][4];
#pragma unroll
            for (int i = 0; i < 4; i++)
#pragma unroll
                for (int j = 0; j < 4; j++) sacc[i][j] = 0.f;
#pragma unroll
            for (int ks = 0; ks < 2; ks++) {
#pragma unroll
                for (int nbp = 0; nbp < 2; nbp++) {
                    uint32_t bf[4];
                    int key = 32 * s + nbp * 16 + (lane & 7) + ((lane >= 16) ? 8 : 0);
                    int col = 16 * ks + ((lane & 8) ? 8 : 0);
                    ldm_x4(bf, smem_u32(&k_s[key * 40 + col]));
                    mma_16816(sacc[2 * nbp],     qa[ks], bf[0], bf[1]);
                    mma_16816(sacc[2 * nbp + 1], qa[ks], bf[2], bf[3]);
                }
            }

            // ---- online softmax (base-2), rescale only when a max improves ----
            float mx0 = sacc[0][0], mx1 = sacc[0][2];
#pragma unroll
            for (int j = 0; j < 4; j++) {
                mx0 = fmaxf(mx0, fmaxf(sacc[j][0], sacc[j][1]));
                mx1 = fmaxf(mx1, fmaxf(sacc[j][2], sacc[j][3]));
            }
#pragma unroll
            for (int off = 1; off < 4; off <<= 1) {
                mx0 = fmaxf(mx0, __shfl_xor_sync(0xffffffffu, mx0, off));
                mx1 = fmaxf(mx1, __shfl_xor_sync(0xffffffffu, mx1, off));
            }
            bool need = __any_sync(0xffffffffu, (mx0 > m0) || (mx1 > m1));
            if (need) {
                float mn0 = fmaxf(m0, mx0), mn1 = fmaxf(m1, mx1);
                float al0 = ex2f(m0 - mn0), al1 = ex2f(m1 - mn1);
                m0 = mn0; m1 = mn1;
#pragma unroll
                for (int nt = 0; nt < 16; nt++) {
                    acc[nt][0] *= al0; acc[nt][1] *= al0;
                    acc[nt][2] *= al1; acc[nt][3] *= al1;
                }
                lacc[0] *= al0; lacc[1] *= al0; lacc[2] *= al1; lacc[3] *= al1;
            }

            // P fragments via f16x2 ex2
            uint32_t pa[2][4];
#pragma unroll
            for (int t = 0; t < 2; t++) {
                pa[t][0] = h2exp2(h2_as_u32(__floats2half2_rn(sacc[2 * t][0] - m0,     sacc[2 * t][1] - m0)));
                pa[t][1] = h2exp2(h2_as_u32(__floats2half2_rn(sacc[2 * t][2] - m1,     sacc[2 * t][3] - m1)));
                pa[t][2] = h2exp2(h2_as_u32(__floats2half2_rn(sacc[2 * t + 1][0] - m0, sacc[2 * t + 1][1] - m0)));
                pa[t][3] = h2exp2(h2_as_u32(__floats2half2_rn(sacc[2 * t + 1][2] - m1, sacc[2 * t + 1][3] - m1)));
            }

            // ---- O += P V : 16 rows x 128 channels ----
#pragma unroll
            for (int t = 0; t < 2; t++) {
#pragma unroll
                for (int nbp = 0; nbp < 8; nbp++) {
                    uint32_t bf[4];
                    int key  = 32 * s + 16 * t + (lane & 15);
                    int chan = nh * 128 + 16 * nbp + ((lane >= 16) ? 8 : 0);
                    ldm_x4_t(bf, smem_u32(&v_s[key * VSTR + chan]));
                    mma_16816(acc[2 * nbp],     pa[t], bf[0], bf[1]);
                    mma_16816(acc[2 * nbp + 1], pa[t], bf[2], bf[3]);
                }
                mma_16816(lacc, pa[t], ONES_H2, ONES_H2);
            }
        }
    }

    // ---- finalize: divide by l, direct fragment writeback ----
    float inv0 = 1.f / lacc[0];
    float inv1 = 1.f / lacc[2];
    int r0 = nq0 + 16 * mw + g;
    int r1 = r0 + 8;
#pragma unroll
    for (int nt = 0; nt < 16; nt++) {
        int c = nh * 128 + 8 * nt + 2 * t4;
        size_t base0 = ((size_t)b * NC + c) * NPIX;
        size_t base1 = ((size_t)b * NC + c + 1) * NPIX;
        out[base0 + r0] = acc[nt][0] * inv0;
        out[base1 + r0] = acc[nt][1] * inv0;
        out[base0 + r1] = acc[nt][2] * inv1;
        out[base1 + r1] = acc[nt][3] * inv1;
    }
}

// ---------------- launcher ----------------
extern "C" void kernel_launch(void* const* d_in, const int* in_sizes, int n_in,
                              void* d_out, int out_size) {
    (void)in_sizes; (void)n_in; (void)out_size;
    const float* x  = (const float*)d_in[0];
    const float* wq = (const float*)d_in[1];
    const float* bq = (const float*)d_in[2];
    const float* wk = (const float*)d_in[3];
    const float* bk = (const float*)d_in[4];
    const float* wv = (const float*)d_in[5];
    const float* bv = (const float*)d_in[6];
    float* out = (float*)d_out;

    pack_w_kernel<<<(MR * NC + 255) / 256, 256>>>(wq, wk, wv);
    pack_x_kernel<<<(NB * NC * NPIX / 4 + 255) / 256, 256>>>(x);

    dim3 pg(NPIX / 64, MR / 64, NB);
    proj_kernel<<<pg, 128>>>(bq, bk, bv);

    cudaFuncSetAttribute(flash_kernel, cudaFuncAttributeMaxDynamicSharedMemorySize, SMEM_TOTAL);
    dim3 fg(NPIX / 128, NB);
    flash_kernel<<<fg, 512, SMEM_TOTAL>>>(out);
}